// round 17
// baseline (speedup 1.0000x reference)
#include <cuda_runtime.h>
#include <cuda_fp16.h>
#include <cstdint>
#include <math.h>

// Problem constants
#define NB   4
#define NH   66
#define NW   66
#define NC   32
#define NF   64
#define HO   64
#define WO   64

// GEMM: per channel K = 176 (9 cij * 18 slots = 162 used, pad to 11 k16-steps)
#define KC        176
#define KI        11                  // k16 steps
#define A_BYTES   (128 * KC * 2)      // 45056 (fragment-major)
#define B_BYTES   (64 * KC * 2)       // 22528 (fragment-major)
#define NOUT      (NB * HO * WO * NF) // 1048576

// smem: two A fragment buffers (B via LDG from L2/L1)
#define SM_A0     0
#define SM_A1     45056
#define SM_TOTAL  90112

// fused prep kernel grid partition
#define PREP_BF_BLOCKS   352          // 90112 threads * 4 halves = 360448 B halves
#define PREP_FEAT_BLOCKS 2178         // 557568 feature elements
#define PREP_INIT_BLOCKS 1024         // 262144 float4 out-init
#define PREP_BLOCKS (PREP_BF_BLOCKS + PREP_FEAT_BLOCKS + PREP_INIT_BLOCKS)

// ---------------------------------------------------------------------------
// Device globals (no allocation allowed)
// B fragment images: [c][ki][ni][lane][4 halves]  (32 * 22528 B = 704 KB, L2-resident)
__device__ __align__(16) __half g_Bfrag[32 * (B_BYTES / 2)];
__device__ __align__(16) float4 g_featP[NC * NB * NH * NW];  // [c][b][h][w]: (t, silu, g-bits, 0)

// ---------------------------------------------------------------------------
__device__ __forceinline__ uint32_t smem_u32(const void* p) {
    uint32_t a;
    asm("{ .reg .u64 t; cvta.to.shared.u64 t, %1; cvt.u32.u64 %0, t; }" : "=r"(a) : "l"(p));
    return a;
}
__device__ __forceinline__ void mma16816(float* d, const uint32_t* a, const uint32_t* b) {
    asm volatile("mma.sync.aligned.m16n8k16.row.col.f32.f16.f16.f32 "
                 "{%0,%1,%2,%3}, {%4,%5,%6,%7}, {%8,%9}, {%0,%1,%2,%3};"
                 : "+f"(d[0]), "+f"(d[1]), "+f"(d[2]), "+f"(d[3])
                 : "r"(a[0]), "r"(a[1]), "r"(a[2]), "r"(a[3]), "r"(b[0]), "r"(b[1]));
}

// A fragment-major byte address for logical element (16-row tile local row16, col)
__device__ __forceinline__ uint32_t a_off(uint32_t base_t, int col) {
    int ki = col >> 4, kk = col & 15;
    return base_t + ki * 512 + (((kk >> 1) & 3) << 4) + ((kk & 1) << 1) + ((kk >> 3) << 3);
}

// ---------------------------------------------------------------------------
// Fused prep kernel: [0,352) B-fragments, [352,2530) features, [2530,3554) out=bias
__global__ void prep_kernel(const float* __restrict__ x,
                            const float* __restrict__ cp,
                            const float* __restrict__ w_spline,
                            const float* __restrict__ w_silu,
                            const float* __restrict__ bias,
                            float* __restrict__ out)
{
    int bid = blockIdx.x;
    int tid = threadIdx.x;

    if (bid < PREP_BF_BLOCKS) {
        int t    = bid * 256 + tid;                 // [0, 90112)
        int lane = t & 31;
        int ni   = (t >> 5) & 7;
        int rest = t >> 8;
        int ki   = rest % KI;
        int c    = rest / KI;
        int gid  = lane >> 2, tig = lane & 3;
        int f    = ni * 8 + gid;
        int kbase = ki * 16 + 2 * tig;
        __half h[4];
#pragma unroll
        for (int bb = 0; bb < 4; bb++) {
            int k = kbase + (bb & 1) + ((bb >> 1) << 3);
            float v = 0.0f;
            if (k < 162) {
                int q = k / 18;
                int s = k - 18 * q;
                int iw = (f * 32 + c) * 9 + q;
                v = (s < 17) ? w_spline[iw] * cp[iw * 17 + s] : w_silu[iw];
            }
            h[bb] = __float2half_rn(v);
        }
        *(uint2*)(g_Bfrag + (size_t)t * 4) = *(const uint2*)h;
    } else if (bid < PREP_BF_BLOCKS + PREP_FEAT_BLOCKS) {
        int i = (bid - PREP_BF_BLOCKS) * 256 + tid;  // [0, 557568)
        int c   = i & 31;
        int pos = i >> 5;
        float v  = x[i];
        float s  = v / (1.0f + __expf(-v));
        float xc = fminf(1.0f, fmaxf(-1.0f, v));
        float u  = (xc + 1.0f) * 8.0f;
        int   g  = (int)u;
        g = (g > 15) ? 15 : g;
        float t  = u - (float)g;
        g_featP[(size_t)c * (NB * NH * NW) + pos] = make_float4(t, s, __int_as_float(g), 0.0f);
    } else {
        int j = (bid - PREP_BF_BLOCKS - PREP_FEAT_BLOCKS) * 256 + tid;  // [0, 262144)
        ((float4*)out)[j] = __ldg(((const float4*)bias) + (j & 15));
    }
}

// ---------------------------------------------------------------------------
// Main HMMA kernel: 256 blocks x 256 threads, 2 blocks/SM (90KB smem, <=128 regs).
// Block = (split s, b, 2 output rows) = 128 px, 16 channels [s*16, +16).
// Warp wm (0..7): OWNS M rows [16*wm, +16) end-to-end — scatters its own A slice
// (lane -> (pixel row16, q-half)) and runs its own MMAs (all 64 f, all 11 ki).
// ZERO cross-warp synchronization in the channel loop: only __syncwarp().
// Per channel: prefetch feat(cc+1) -> syncwarp -> MMA(cc) -> scatter(cc+1).
__global__ void __launch_bounds__(256, 2)
kan_hmma_kernel(float* __restrict__ out)
{
    extern __shared__ char smem[];
    const uint32_t sbase = smem_u32(smem);
    const int tid  = threadIdx.x;
    const int wm   = tid >> 5;            // warp id == M tile id (16 rows)
    const int lane = tid & 31;
    const int blk  = blockIdx.x;
    const int s    = blk >> 7;            // channel split (0,1)
    const int b    = (blk >> 5) & 3;
    const int h0   = (blk & 31) * 2;
    const int c0   = s * 16;

    // zero both A fragment buffers (cols never written stay 0 forever)
    {
        float4* az = (float4*)smem;
#pragma unroll 4
        for (int i = tid; i < (2 * A_BYTES) / 16; i += 256) az[i] = make_float4(0.f, 0.f, 0.f, 0.f);
    }
    __syncthreads();   // A zeroing visible before scatter (only block-wide sync)

    // warp-local scatter config: lane -> pixel row16 = lane&15, q-half = lane>>4
    // half 0: q 0..4 (5 groups); half 1: q 5..8 (4 groups)
    const int px16  = lane & 15;
    const int half  = lane >> 4;
    const int qbase = half ? 5 : 0;
    const int qcnt  = half ? 4 : 5;
    const int px    = wm * 16 + px16;
    const int rh    = px >> 6, rw = px & 63;
    const uint32_t base_t0 = (uint32_t)(wm * 5632 + ((px16 & 7) << 6) + ((px16 >> 3) << 2));

    float acc[8][4];
#pragma unroll
    for (int nt = 0; nt < 8; nt++)
#pragma unroll
        for (int e = 0; e < 4; e++) acc[nt][e] = 0.0f;

    uint32_t gpack[2] = {0u, 0u};

    // feat loads for channel cc (<=5 per thread) into registers
    auto loadFeat = [&](int cc, float4* fv) {
        int ca = c0 + cc;
#pragma unroll
        for (int qi = 0; qi < 5; qi++) {
            if (qi >= qcnt) break;
            int q  = qbase + qi;
            int ii = q / 3, jj = q - 3 * ii;
            fv[qi] = __ldg(g_featP + ((size_t)(ca * NB + b) * NH + (h0 + rh + ii)) * NW + (rw + jj));
        }
    };
    // scatter channel cc from regs into buffer cc&1 (zero stale slots from cc-2)
    auto scatter = [&](int cc, const float4* fv) {
        char* Ab = smem + ((cc & 1) ? SM_A1 : SM_A0);
#pragma unroll
        for (int qi = 0; qi < 5; qi++) {
            if (qi >= qcnt) break;
            int q = qbase + qi;
            int g = __float_as_int(fv[qi].z);
            if (cc >= 2) {
                int gold = (gpack[cc & 1] >> (4 * qi)) & 15;
                int oc   = q * 18 + gold;
                *(__half*)(Ab + a_off(base_t0, oc))     = __ushort_as_half((unsigned short)0);
                *(__half*)(Ab + a_off(base_t0, oc + 1)) = __ushort_as_half((unsigned short)0);
            }
            int col0 = q * 18 + g;
            *(__half*)(Ab + a_off(base_t0, col0))        = __float2half_rn(1.0f - fv[qi].x);
            *(__half*)(Ab + a_off(base_t0, col0 + 1))    = __float2half_rn(fv[qi].x);
            *(__half*)(Ab + a_off(base_t0, q * 18 + 17)) = __float2half_rn(fv[qi].y);
            gpack[cc & 1] = (gpack[cc & 1] & ~(15u << (4 * qi))) | ((uint32_t)g << (4 * qi));
        }
    };

    {
        float4 fv[5];
        loadFeat(0, fv);
        scatter(0, fv);
    }

    for (int cc = 0; cc < 16; cc++) {
        const int buf = cc & 1;

        // prefetch feats for cc+1 (L2 latency hides under this channel's MMAs)
        float4 fv[5];
        if (cc < 15) loadFeat(cc + 1, fv);

        // order own-warp scatter(cc) STS before MMA(cc) LDS across lanes
        __syncwarp();

        // ---- MMA(cc): A via LDS (warp-local), B via LDG quad-pipelined ----
        {
            const uint32_t abase = sbase + (buf ? SM_A1 : SM_A0)
                                 + (uint32_t)(wm * 5632 + lane * 16);
            const __half* Bc = g_Bfrag + (size_t)(c0 + cc) * (B_BYTES / 2) + lane * 4;
            uint2 bq[4], bn[4];
#pragma unroll
            for (int nt = 0; nt < 4; nt++)
                bq[nt] = __ldg((const uint2*)(Bc + (size_t)nt * 128));
#pragma unroll
            for (int ki = 0; ki < KI; ki++) {
                // issue quad1 loads for this ki
#pragma unroll
                for (int nt = 0; nt < 4; nt++)
                    bn[nt] = __ldg((const uint2*)(Bc + (size_t)(ki * 8 + 4 + nt) * 128));
                // A fragment (one m16 tile)
                uint32_t afr[4];
                asm volatile("ld.shared.v4.b32 {%0,%1,%2,%3}, [%4];"
                             : "=r"(afr[0]), "=r"(afr[1]), "=r"(afr[2]), "=r"(afr[3])
                             : "r"(abase + (uint32_t)(ki * 512)));
                // MMA quad0 (nt 0..3)
#pragma unroll
                for (int nt = 0; nt < 4; nt++)
                    mma16816(acc[nt], afr, (const uint32_t*)&bq[nt]);
                // preload next ki's quad0
                uint2 bq2[4];
                if (ki < KI - 1) {
#pragma unroll
                    for (int nt = 0; nt < 4; nt++)
                        bq2[nt] = __ldg((const uint2*)(Bc + (size_t)((ki + 1) * 8 + nt) * 128));
                }
                // MMA quad1 (nt 4..7)
#pragma unroll
                for (int nt = 0; nt < 4; nt++)
                    mma16816(acc[4 + nt], afr, (const uint32_t*)&bn[nt]);
                if (ki < KI - 1) {
#pragma unroll
                    for (int nt = 0; nt < 4; nt++) bq[nt] = bq2[nt];
                }
            }
        }

        // ---- scatter(cc+1) into the opposite A buffer (warp-local) ----
        if (cc < 15) scatter(cc + 1, fv);
    }

    // ---- epilogue: direct RED.ADD into bias-initialized out (warp-local rows) ----
    {
        const int gid = lane >> 2, tig = lane & 3;
#pragma unroll
        for (int nt = 0; nt < 8; nt++) {
            int f  = nt * 8 + 2 * tig;
            int r0 = wm * 16 + gid;
            int r1 = r0 + 8;
            float* o0 = out + (((size_t)(b * HO) + (h0 + (r0 >> 6))) * WO + (r0 & 63)) * NF + f;
            float* o1 = out + (((size_t)(b * HO) + (h0 + (r1 >> 6))) * WO + (r1 & 63)) * NF + f;
            atomicAdd(o0,     acc[nt][0]);
            atomicAdd(o0 + 1, acc[nt][1]);
            atomicAdd(o1,     acc[nt][2]);
            atomicAdd(o1 + 1, acc[nt][3]);
        }
    }
}

// ---------------------------------------------------------------------------
extern "C" void kernel_launch(void* const* d_in, const int* in_sizes, int n_in,
                              void* d_out, int out_size)
{
    const float* x    = (const float*)d_in[0];   // (4,66,66,32)
    const float* cp   = (const float*)d_in[1];   // (64,32,3,3,17)
    const float* wsp  = (const float*)d_in[2];   // (64,32,3,3)
    const float* wsi  = (const float*)d_in[3];   // (64,32,3,3)
    const float* bias = (const float*)d_in[4];   // (64,)
    float* out        = (float*)d_out;           // (4,64,64,64)

    cudaFuncSetAttribute(kan_hmma_kernel, cudaFuncAttributeMaxDynamicSharedMemorySize, SM_TOTAL);

    prep_kernel<<<PREP_BLOCKS, 256>>>(x, cp, wsp, wsi, bias, out);
    kan_hmma_kernel<<<256, 256, SM_TOTAL>>>(out);
}